// round 16
// baseline (speedup 1.0000x reference)
#include <cuda_runtime.h>
#include <cuda_bf16.h>
#include <cstdint>

#define BATCH 4
#define CHN   256
#define SEQ   4096
#define DV    128
#define QT    128
#define MT    64
#define NTILE (SEQ / MT)
#define LOG2E 1.4426950408889634f

// ---------------------------------------------------------------------------
// Device scratch (no allocation allowed)
// ---------------------------------------------------------------------------
__device__ __align__(16) __nv_bfloat16 g_wch[192 * 256];  // concat(Wt,Wp,Wg) hi
__device__ __align__(16) __nv_bfloat16 g_wcl[192 * 256];  // lo
__device__ __align__(16) __nv_bfloat16 g_woh[256 * 128];  // Wo hi
__device__ __align__(16) __nv_bfloat16 g_wol[256 * 128];  // Wo lo
__device__ __align__(16) __nv_bfloat16 g_xth[(size_t)BATCH * SEQ * CHN]; // x^T hi [b][n][c]
__device__ __align__(16) __nv_bfloat16 g_xtl[(size_t)BATCH * SEQ * CHN]; // x^T lo
__device__ __align__(16) __nv_bfloat16 g_th_t[(size_t)BATCH * SEQ * 64]; // theta^T [n][32hi|32lo]
__device__ __align__(16) __nv_bfloat16 g_ph_t[(size_t)BATCH * SEQ * 64]; // phi^T (x log2e)
__device__ __align__(16) __nv_bfloat16 g_vth[(size_t)BATCH * SEQ * DV];  // g^T hi [b][n][c]
__device__ __align__(16) __nv_bfloat16 g_ath[(size_t)BATCH * SEQ * DV];  // attn^T hi [b][n][c]
__device__ __align__(16) __nv_bfloat16 g_atl[(size_t)BATCH * SEQ * DV];  // attn^T lo

// ---------------------------------------------------------------------------
// Base-ISA PTX helpers
// ---------------------------------------------------------------------------
__device__ __forceinline__ uint32_t smem_u32(const void* p) {
    uint32_t a;
    asm("{ .reg .u64 t; cvta.to.shared.u64 t, %1; cvt.u32.u64 %0, t; }" : "=r"(a) : "l"(p));
    return a;
}
__device__ __forceinline__ void cpa16(uint32_t dst, const void* src) {
    asm volatile("cp.async.cg.shared.global [%0], [%1], 16;" :: "r"(dst), "l"(src));
}
#define CP_COMMIT() asm volatile("cp.async.commit_group;" ::: "memory")
#define CP_WAIT0()  asm volatile("cp.async.wait_group 0;" ::: "memory")
#define CP_WAIT1()  asm volatile("cp.async.wait_group 1;" ::: "memory")

__device__ __forceinline__ void ldsm4(uint32_t* r, uint32_t addr) {
    asm volatile("ldmatrix.sync.aligned.m8n8.x4.shared.b16 {%0,%1,%2,%3}, [%4];"
                 : "=r"(r[0]), "=r"(r[1]), "=r"(r[2]), "=r"(r[3]) : "r"(addr));
}
__device__ __forceinline__ void ldsm4_t(uint32_t* r, uint32_t addr) {
    asm volatile("ldmatrix.sync.aligned.m8n8.x4.trans.shared.b16 {%0,%1,%2,%3}, [%4];"
                 : "=r"(r[0]), "=r"(r[1]), "=r"(r[2]), "=r"(r[3]) : "r"(addr));
}
__device__ __forceinline__ void mma_bf16(float* d, const uint32_t* a, uint32_t b0, uint32_t b1) {
    asm volatile(
        "mma.sync.aligned.m16n8k16.row.col.f32.bf16.bf16.f32 "
        "{%0,%1,%2,%3}, {%4,%5,%6,%7}, {%8,%9}, {%0,%1,%2,%3};"
        : "+f"(d[0]), "+f"(d[1]), "+f"(d[2]), "+f"(d[3])
        : "r"(a[0]), "r"(a[1]), "r"(a[2]), "r"(a[3]), "r"(b0), "r"(b1));
}
__device__ __forceinline__ float ex2f(float x) {
    float y;
    asm("ex2.approx.ftz.f32 %0, %1;" : "=f"(y) : "f"(x));
    return y;
}
__device__ __forceinline__ uint32_t cvt2(float a, float b) {   // bf16x2 {lo=a, hi=b}
    uint32_t r;
    asm("cvt.rn.bf16x2.f32 %0, %1, %2;" : "=r"(r) : "f"(b), "f"(a));
    return r;
}
__device__ __forceinline__ void split2(float a, float b, uint32_t& hw, uint32_t& lw) {
    hw = cvt2(a, b);
    float ha = __uint_as_float(hw << 16);
    float hb = __uint_as_float(hw & 0xffff0000u);
    lw = cvt2(a - ha, b - hb);
}

// ---------------------------------------------------------------------------
// Prep kernels
// ---------------------------------------------------------------------------
__global__ void prep_w_kernel(const float* __restrict__ Wt, const float* __restrict__ Wp,
                              const float* __restrict__ Wg, const float* __restrict__ Wo) {
    int r = blockIdx.x, c = threadIdx.x;
    if (r < 192) {
        float v = (r < 32) ? Wt[r * CHN + c]
                 : (r < 64) ? Wp[(r - 32) * CHN + c]
                            : Wg[(r - 64) * CHN + c];
        __nv_bfloat16 h = __float2bfloat16(v);
        g_wch[r * CHN + c] = h;
        g_wcl[r * CHN + c] = __float2bfloat16(v - __bfloat162float(h));
    } else if (c < 128) {
        int rr = r - 192;
        float v = Wo[rr * DV + c];
        __nv_bfloat16 h = __float2bfloat16(v);
        g_woh[rr * DV + c] = h;
        g_wol[rr * DV + c] = __float2bfloat16(v - __bfloat162float(h));
    }
}

// x [b][256][4096] -> x^T hi/lo [b][4096][256]
__global__ void transpose_x_kernel(const float* __restrict__ Xg) {
    __shared__ float tile[32][33];
    int b  = blockIdx.z;
    int n0 = blockIdx.x * 32;
    int c0 = blockIdx.y * 32;
    int tx = threadIdx.x & 31, ty = threadIdx.x >> 5;
    const float* xb = Xg + (size_t)b * CHN * SEQ;
#pragma unroll
    for (int i = 0; i < 32; i += 8)
        tile[ty + i][tx] = xb[(size_t)(c0 + ty + i) * SEQ + n0 + tx];
    __syncthreads();
#pragma unroll
    for (int i = 0; i < 32; i += 8) {
        float v = tile[tx][ty + i];
        __nv_bfloat16 h = __float2bfloat16(v);
        size_t off = ((size_t)b * SEQ + n0 + ty + i) * CHN + c0 + tx;
        g_xth[off] = h;
        g_xtl[off] = __float2bfloat16(v - __bfloat162float(h));
    }
}

// ---------------------------------------------------------------------------
// Projection GEMM via mma.sync: C[n][out192] = x^T[n][c] * Wcat[out][c]
// ---------------------------------------------------------------------------
#define PJ_SMEM 110592
__global__ __launch_bounds__(256, 1) void proj_mma_kernel() {
    extern __shared__ char sm[];
    const uint32_t smb = smem_u32(sm);
    const int b    = blockIdx.z;
    const int out0 = blockIdx.y * 64;
    const int n0   = blockIdx.x * 128;
    const int tid  = threadIdx.x;
    const int w    = tid >> 5;
    const int lane = tid & 31;
    const uint32_t lm = lane & 7;
    const uint32_t bk = (lane >> 3) & 1;
    const uint32_t bn = (lane >> 4) & 1;

    auto load_chunk = [&](int buf, int k0) {
        uint32_t base = smb + buf * 55296;
        const char* xh = (const char*)(g_xth + ((size_t)b * SEQ + n0) * CHN + k0);
        const char* xl = (const char*)(g_xtl + ((size_t)b * SEQ + n0) * CHN + k0);
        for (int e = tid; e < 1024; e += 256) {
            int r = e >> 3, s = e & 7;
            cpa16(base + r * 144 + s * 16,         xh + (size_t)r * 512 + s * 16);
            cpa16(base + 18432 + r * 144 + s * 16, xl + (size_t)r * 512 + s * 16);
        }
        const char* wh = (const char*)(g_wch + (size_t)out0 * CHN + k0);
        const char* wl = (const char*)(g_wcl + (size_t)out0 * CHN + k0);
        for (int e = tid; e < 512; e += 256) {
            int r = e >> 3, s = e & 7;
            cpa16(base + 36864 + r * 144 + s * 16, wh + (size_t)r * 512 + s * 16);
            cpa16(base + 46080 + r * 144 + s * 16, wl + (size_t)r * 512 + s * 16);
        }
    };

    float oacc[8][4];
#pragma unroll
    for (int g = 0; g < 8; g++)
#pragma unroll
        for (int k = 0; k < 4; k++) oacc[g][k] = 0.f;

    load_chunk(0, 0);
    CP_COMMIT();

    for (int kb = 0; kb < 4; kb++) {
        int buf = kb & 1;
        if (kb < 3) { load_chunk(buf ^ 1, (kb + 1) * 64); CP_COMMIT(); CP_WAIT1(); }
        else        { CP_WAIT0(); }
        __syncthreads();

        uint32_t ab = smb + buf * 55296;
        uint32_t bb = ab + 36864;
#pragma unroll
        for (int kc = 0; kc < 4; kc++) {
            uint32_t ah4[4], al4[4];
            uint32_t aaddr = ab + (w * 16 + bk * 8 + lm) * 144 + (kc * 16 + bn * 8) * 2;
            ldsm4(ah4, aaddr);
            ldsm4(al4, aaddr + 18432);
#pragma unroll
            for (int jj = 0; jj < 4; jj++) {
                uint32_t baddr = bb + (jj * 16 + bn * 8 + lm) * 144 + (kc * 16 + bk * 8) * 2;
                uint32_t bh4[4], bl4[4];
                ldsm4(bh4, baddr);
                ldsm4(bl4, baddr + 9216);
                mma_bf16(oacc[2 * jj],     ah4, bh4[0], bh4[1]);
                mma_bf16(oacc[2 * jj],     ah4, bl4[0], bl4[1]);
                mma_bf16(oacc[2 * jj],     al4, bh4[0], bh4[1]);
                mma_bf16(oacc[2 * jj + 1], ah4, bh4[2], bh4[3]);
                mma_bf16(oacc[2 * jj + 1], ah4, bl4[2], bl4[3]);
                mma_bf16(oacc[2 * jj + 1], al4, bh4[2], bh4[3]);
            }
        }
        __syncthreads();
    }

    // epilogue
    const int rbase = n0 + w * 16 + (lane >> 2);
    const int qc = (lane & 3) * 2;
#pragma unroll
    for (int g = 0; g < 8; g++) {
        int out = out0 + g * 8 + qc;
#pragma unroll
        for (int rr = 0; rr < 2; rr++) {
            int n = rbase + rr * 8;
            float v0 = oacc[g][rr * 2], v1 = oacc[g][rr * 2 + 1];
            uint32_t hw, lw;
            if (out < 32) {
                split2(v0, v1, hw, lw);
                __nv_bfloat16* base = g_th_t + ((size_t)b * SEQ + n) * 64;
                *(uint32_t*)(base + out) = hw;
                *(uint32_t*)(base + 32 + out) = lw;
            } else if (out < 64) {
                split2(v0 * LOG2E, v1 * LOG2E, hw, lw);
                __nv_bfloat16* base = g_ph_t + ((size_t)b * SEQ + n) * 64;
                *(uint32_t*)(base + (out - 32)) = hw;
                *(uint32_t*)(base + out) = lw;
            } else {
                size_t off = ((size_t)b * SEQ + n) * DV + (out - 64);
                *(uint32_t*)(g_vth + off) = cvt2(v0, v1);   // bf16 hi only
            }
        }
    }
}

// ---------------------------------------------------------------------------
// Flash attention (mma.sync; S 3-term bf16, PV (ph+pl)*vh, no-max softmax).
// 4-deep K/V buffers, 2 tiles per __syncthreads; warps w and w+4 (which share
// an SMSP: smsp = wid%4) process the tile pair in OPPOSITE order so softmax
// and MMA phases anti-phase on every scheduler.
// Smem: QHI 0..10240 QLO 10240..20480 (80B rows)
//       K buf b: 20480 + b*10240 (hi, +5120 lo), b in 0..3
//       V buf b: 61440 + b*17408 ([64 m][272B] bf16 hi), b in 0..3
// Total 131072 (1 CTA/SM).
// ---------------------------------------------------------------------------
#define SM_QHI 0
#define SM_QLO 10240
#define SM_K   20480
#define SM_V   61440
#define FLASH_SMEM 131072

__global__ __launch_bounds__(256, 1) void flash_mma_kernel() {
    extern __shared__ char sm[];
    const uint32_t smb = smem_u32(sm);

    const int b  = blockIdx.y;
    const int q0 = blockIdx.x * QT;
    const int tid  = threadIdx.x;
    const int w    = tid >> 5;
    const int lane = tid & 31;
    const uint32_t lm = lane & 7;
    const uint32_t bk = (lane >> 3) & 1;
    const uint32_t bn = (lane >> 4) & 1;

    auto load_kv = [&](int buf, int m0) {
        const char* ks = (const char*)(g_ph_t + ((size_t)b * SEQ + m0) * 64);
        uint32_t kb = smb + SM_K + buf * 10240;
        for (int e = tid; e < 512; e += 256) {
            int r = e >> 3, s = e & 7;
            uint32_t dst = kb + (s < 4 ? (r * 80 + s * 16) : (5120 + r * 80 + (s - 4) * 16));
            cpa16(dst, ks + r * 128 + s * 16);
        }
        const char* vh = (const char*)(g_vth + ((size_t)b * SEQ + m0) * DV);
        uint32_t vb = smb + SM_V + buf * 17408;
        for (int e = tid; e < 1024; e += 256) {
            int r = e >> 4, s = e & 15;
            cpa16(vb + r * 272 + s * 16, vh + (size_t)r * 256 + s * 16);
        }
    };

    // Q tile + first two K/V tiles
    {
        const char* src = (const char*)(g_th_t + ((size_t)b * SEQ + q0) * 64);
        for (int e = tid; e < 1024; e += 256) {
            int r = e >> 3, s = e & 7;
            uint32_t dst = smb + (s < 4 ? (SM_QHI + r * 80 + s * 16)
                                        : (SM_QLO + r * 80 + (s - 4) * 16));
            cpa16(dst, src + r * 128 + s * 16);
        }
    }
    load_kv(0, 0);
    CP_COMMIT();
    load_kv(1, MT);
    CP_COMMIT();
    CP_WAIT0();
    __syncthreads();

    uint32_t qh[2][4], ql[2][4];
#pragma unroll
    for (int ks = 0; ks < 2; ks++) {
        uint32_t a = smb + SM_QHI + (w * 16 + bk * 8 + lm) * 80 + (ks * 16 + bn * 8) * 2;
        ldsm4(qh[ks], a);
        ldsm4(ql[ks], a + (SM_QLO - SM_QHI));
    }

    float oacc[16][4];
#pragma unroll
    for (int j = 0; j < 16; j++)
#pragma unroll
        for (int k = 0; k < 4; k++) oacc[j][k] = 0.f;
    float l0 = 0.f, l1 = 0.f;

    // process one tile from buffer `buf`
    auto proc_tile = [&](int buf) {
        // S = Q K^T (3-term)
        float sacc[8][4];
#pragma unroll
        for (int j = 0; j < 8; j++)
#pragma unroll
            for (int k = 0; k < 4; k++) sacc[j][k] = 0.f;

        const uint32_t kb = smb + SM_K + buf * 10240;
#pragma unroll
        for (int ks = 0; ks < 2; ks++) {
#pragma unroll
            for (int jj = 0; jj < 4; jj++) {
                uint32_t addr = kb + (jj * 16 + bn * 8 + lm) * 80 + (ks * 16 + bk * 8) * 2;
                uint32_t kh[4], kl[4];
                ldsm4(kh, addr);
                ldsm4(kl, addr + 5120);
                mma_bf16(sacc[2 * jj],     qh[ks], kh[0], kh[1]);
                mma_bf16(sacc[2 * jj],     qh[ks], kl[0], kl[1]);
                mma_bf16(sacc[2 * jj],     ql[ks], kh[0], kh[1]);
                mma_bf16(sacc[2 * jj + 1], qh[ks], kh[2], kh[3]);
                mma_bf16(sacc[2 * jj + 1], qh[ks], kl[2], kl[3]);
                mma_bf16(sacc[2 * jj + 1], ql[ks], kh[2], kh[3]);
            }
        }

        // softmax numerators (phi prescaled by log2e); split P hi/lo
        uint32_t ph_[8][2], pl_[8][2];
#pragma unroll
        for (int j = 0; j < 8; j++) {
            float p0 = ex2f(sacc[j][0]);
            float p1 = ex2f(sacc[j][1]);
            float p2 = ex2f(sacc[j][2]);
            float p3 = ex2f(sacc[j][3]);
            l0 += p0 + p1;
            l1 += p2 + p3;
            split2(p0, p1, ph_[j][0], pl_[j][0]);
            split2(p2, p3, ph_[j][1], pl_[j][1]);
        }

        // O += (Phi + Plo) V^T
        const uint32_t vb = smb + SM_V + buf * 17408;
#pragma unroll
        for (int kk = 0; kk < 4; kk++) {
            uint32_t pah[4] = {ph_[2 * kk][0], ph_[2 * kk][1], ph_[2 * kk + 1][0], ph_[2 * kk + 1][1]};
            uint32_t pal[4] = {pl_[2 * kk][0], pl_[2 * kk][1], pl_[2 * kk + 1][0], pl_[2 * kk + 1][1]};
#pragma unroll
            for (int jj = 0; jj < 8; jj++) {
                uint32_t addr = vb + (kk * 16 + bk * 8 + lm) * 272 + (jj * 16 + bn * 8) * 2;
                uint32_t vh4[4];
                ldsm4_t(vh4, addr);
                mma_bf16(oacc[2 * jj],     pah, vh4[0], vh4[1]);
                mma_bf16(oacc[2 * jj],     pal, vh4[0], vh4[1]);
                mma_bf16(oacc[2 * jj + 1], pah, vh4[2], vh4[3]);
                mma_bf16(oacc[2 * jj + 1], pal, vh4[2], vh4[3]);
            }
        }
    };

    // Anti-phase across SMSP partners: smsp = w % 4, partners are w and w+4.
    const int swap = (w >> 2) & 1;   // warps 0-3 forward, warps 4-7 reverse
    for (int it = 0; it < NTILE; it += 2) {
        // tiles it, it+1 are resident; prefetch it+2, it+3
        if (it + 2 < NTILE) { load_kv((it + 2) & 3, (it + 2) * MT); CP_COMMIT(); }
        if (it + 3 < NTILE) { load_kv((it + 3) & 3, (it + 3) * MT); CP_COMMIT(); }

        proc_tile((it + swap) & 3);
        proc_tile((it + (swap ^ 1)) & 3);

        CP_WAIT0();
        __syncthreads();
    }

    // epilogue: reduce row sums, normalize, write attn^T hi/lo bf16
    l0 += __shfl_xor_sync(0xffffffffu, l0, 1);
    l0 += __shfl_xor_sync(0xffffffffu, l0, 2);
    l1 += __shfl_xor_sync(0xffffffffu, l1, 1);
    l1 += __shfl_xor_sync(0xffffffffu, l1, 2);
    const float inv0 = 1.f / l0;
    const float inv1 = 1.f / l1;

    const int r0 = q0 + w * 16 + (lane >> 2);
    const int qc = (lane & 3) * 2;
#pragma unroll
    for (int j = 0; j < 16; j++) {
        int c = j * 8 + qc;
        uint32_t hw, lw;
        split2(oacc[j][0] * inv0, oacc[j][1] * inv0, hw, lw);
        size_t off = ((size_t)b * SEQ + r0) * DV + c;
        *(uint32_t*)(g_ath + off) = hw;
        *(uint32_t*)(g_atl + off) = lw;
        split2(oacc[j][2] * inv1, oacc[j][3] * inv1, hw, lw);
        size_t off2 = ((size_t)b * SEQ + r0 + 8) * DV + c;
        *(uint32_t*)(g_ath + off2) = hw;
        *(uint32_t*)(g_atl + off2) = lw;
    }
}

// ---------------------------------------------------------------------------
// Output GEMM via mma.sync
// ---------------------------------------------------------------------------
#define OM_SMEM 104448
__global__ __launch_bounds__(256) void out_mma_kernel(const float* __restrict__ Xg,
                                                      float* __restrict__ Cg,
                                                      const float* __restrict__ gamma_p) {
    extern __shared__ char sm[];
    const uint32_t smb = smem_u32(sm);
    const int b  = blockIdx.z;
    const int n0 = blockIdx.x * 64;
    const int m0 = blockIdx.y * 128;
    const int tid  = threadIdx.x;
    const int w    = tid >> 5;
    const int lane = tid & 31;
    const uint32_t lm = lane & 7;
    const uint32_t bk = (lane >> 3) & 1;
    const uint32_t bn = (lane >> 4) & 1;

    {
        const char* ah = (const char*)(g_woh + (size_t)m0 * DV);
        const char* al = (const char*)(g_wol + (size_t)m0 * DV);
        for (int e = tid; e < 2048; e += 256) {
            int r = e >> 4, s = e & 15;
            cpa16(smb + r * 272 + s * 16,         ah + (size_t)r * 256 + s * 16);
            cpa16(smb + 34816 + r * 272 + s * 16, al + (size_t)r * 256 + s * 16);
        }
        const char* bh = (const char*)(g_ath + ((size_t)b * SEQ + n0) * DV);
        const char* bl = (const char*)(g_atl + ((size_t)b * SEQ + n0) * DV);
        for (int e = tid; e < 1024; e += 256) {
            int r = e >> 4, s = e & 15;
            cpa16(smb + 69632 + r * 272 + s * 16, bh + (size_t)r * 256 + s * 16);
            cpa16(smb + 87040 + r * 272 + s * 16, bl + (size_t)r * 256 + s * 16);
        }
    }
    CP_COMMIT();
    CP_WAIT0();
    __syncthreads();

    float oacc[8][4];
#pragma unroll
    for (int g = 0; g < 8; g++)
#pragma unroll
        for (int k = 0; k < 4; k++) oacc[g][k] = 0.f;

#pragma unroll
    for (int kc = 0; kc < 8; kc++) {
        uint32_t ah4[4], al4[4];
        uint32_t aaddr = smb + (w * 16 + bk * 8 + lm) * 272 + (kc * 16 + bn * 8) * 2;
        ldsm4(ah4, aaddr);
        ldsm4(al4, aaddr + 34816);
#pragma unroll
        for (int jj = 0; jj < 4; jj++) {
            uint32_t baddr = smb + 69632 + (jj * 16 + bn * 8 + lm) * 272 + (kc * 16 + bk * 8) * 2;
            uint32_t bh4[4], bl4[4];
            ldsm4(bh4, baddr);
            ldsm4(bl4, baddr + 17408);
            mma_bf16(oacc[2 * jj],     ah4, bh4[0], bh4[1]);
            mma_bf16(oacc[2 * jj],     ah4, bl4[0], bl4[1]);
            mma_bf16(oacc[2 * jj],     al4, bh4[0], bh4[1]);
            mma_bf16(oacc[2 * jj + 1], ah4, bh4[2], bh4[3]);
            mma_bf16(oacc[2 * jj + 1], ah4, bl4[2], bl4[3]);
            mma_bf16(oacc[2 * jj + 1], al4, bh4[2], bh4[3]);
        }
    }

    const float gm = gamma_p[0];
    const float* xb = Xg + (size_t)b * CHN * SEQ;
    float* cb = Cg + (size_t)b * CHN * SEQ;
    const int r = m0 + w * 16 + (lane >> 2);
    const int qc = (lane & 3) * 2;
#pragma unroll
    for (int g = 0; g < 8; g++) {
        int n = n0 + g * 8 + qc;
#pragma unroll
        for (int rr = 0; rr < 2; rr++) {
            int row = r + rr * 8;
            float2 x2 = *(const float2*)(xb + (size_t)row * SEQ + n);
            float2 o;
            o.x = gm * oacc[g][rr * 2]     + x2.x;
            o.y = gm * oacc[g][rr * 2 + 1] + x2.y;
            *(float2*)(cb + (size_t)row * SEQ + n) = o;
        }
    }
}

// ---------------------------------------------------------------------------
// Launch
// ---------------------------------------------------------------------------
extern "C" void kernel_launch(void* const* d_in, const int* in_sizes, int n_in,
                              void* d_out, int out_size) {
    const float* x     = (const float*)d_in[0];
    const float* Wt    = (const float*)d_in[1];
    const float* Wp    = (const float*)d_in[2];
    const float* Wg    = (const float*)d_in[3];
    const float* Wo    = (const float*)d_in[4];
    const float* gamma = (const float*)d_in[5];
    float* out = (float*)d_out;
    (void)in_sizes; (void)n_in; (void)out_size;

    prep_w_kernel<<<448, 256>>>(Wt, Wp, Wg, Wo);
    transpose_x_kernel<<<dim3(SEQ / 32, CHN / 32, BATCH), 256>>>(x);

    cudaFuncSetAttribute(proj_mma_kernel, cudaFuncAttributeMaxDynamicSharedMemorySize, PJ_SMEM);
    proj_mma_kernel<<<dim3(SEQ / 128, 3, BATCH), 256, PJ_SMEM>>>();

    cudaFuncSetAttribute(flash_mma_kernel, cudaFuncAttributeMaxDynamicSharedMemorySize, FLASH_SMEM);
    flash_mma_kernel<<<dim3(SEQ / QT, BATCH), 256, FLASH_SMEM>>>();

    cudaFuncSetAttribute(out_mma_kernel, cudaFuncAttributeMaxDynamicSharedMemorySize, OM_SMEM);
    out_mma_kernel<<<dim3(SEQ / 64, CHN / 128, BATCH), 256, OM_SMEM>>>(x, out, gamma);
}

// round 17
// speedup vs baseline: 1.5703x; 1.5703x over previous
#include <cuda_runtime.h>
#include <cuda_bf16.h>
#include <cstdint>

#define BATCH 4
#define CHN   256
#define SEQ   4096
#define DV    128
#define QT    128
#define MT    64
#define NTILE (SEQ / MT)
#define LOG2E 1.4426950408889634f

// ---------------------------------------------------------------------------
// Device scratch (no allocation allowed)
// ---------------------------------------------------------------------------
__device__ __align__(16) __nv_bfloat16 g_wch[192 * 256];  // concat(Wt,Wp,Wg) hi
__device__ __align__(16) __nv_bfloat16 g_wcl[192 * 256];  // lo
__device__ __align__(16) __nv_bfloat16 g_woh[256 * 128];  // Wo hi
__device__ __align__(16) __nv_bfloat16 g_wol[256 * 128];  // Wo lo
__device__ __align__(16) __nv_bfloat16 g_xth[(size_t)BATCH * SEQ * CHN]; // x^T hi [b][n][c]
__device__ __align__(16) __nv_bfloat16 g_xtl[(size_t)BATCH * SEQ * CHN]; // x^T lo
__device__ __align__(16) __nv_bfloat16 g_th_t[(size_t)BATCH * SEQ * 64]; // theta^T [n][32hi|32lo]
__device__ __align__(16) __nv_bfloat16 g_ph_t[(size_t)BATCH * SEQ * 64]; // phi^T (x log2e)
__device__ __align__(16) __nv_bfloat16 g_vth[(size_t)BATCH * SEQ * DV];  // g^T hi [b][n][c]
__device__ __align__(16) __nv_bfloat16 g_ath[(size_t)BATCH * SEQ * DV];  // attn^T hi [b][n][c]
__device__ __align__(16) __nv_bfloat16 g_atl[(size_t)BATCH * SEQ * DV];  // attn^T lo

// ---------------------------------------------------------------------------
// Base-ISA PTX helpers
// ---------------------------------------------------------------------------
__device__ __forceinline__ uint32_t smem_u32(const void* p) {
    uint32_t a;
    asm("{ .reg .u64 t; cvta.to.shared.u64 t, %1; cvt.u32.u64 %0, t; }" : "=r"(a) : "l"(p));
    return a;
}
__device__ __forceinline__ void cpa16(uint32_t dst, const void* src) {
    asm volatile("cp.async.cg.shared.global [%0], [%1], 16;" :: "r"(dst), "l"(src));
}
#define CP_COMMIT() asm volatile("cp.async.commit_group;" ::: "memory")
#define CP_WAIT0()  asm volatile("cp.async.wait_group 0;" ::: "memory")
#define CP_WAIT1()  asm volatile("cp.async.wait_group 1;" ::: "memory")

__device__ __forceinline__ void ldsm4(uint32_t* r, uint32_t addr) {
    asm volatile("ldmatrix.sync.aligned.m8n8.x4.shared.b16 {%0,%1,%2,%3}, [%4];"
                 : "=r"(r[0]), "=r"(r[1]), "=r"(r[2]), "=r"(r[3]) : "r"(addr));
}
__device__ __forceinline__ void ldsm4_t(uint32_t* r, uint32_t addr) {
    asm volatile("ldmatrix.sync.aligned.m8n8.x4.trans.shared.b16 {%0,%1,%2,%3}, [%4];"
                 : "=r"(r[0]), "=r"(r[1]), "=r"(r[2]), "=r"(r[3]) : "r"(addr));
}
__device__ __forceinline__ void mma_bf16(float* d, const uint32_t* a, uint32_t b0, uint32_t b1) {
    asm volatile(
        "mma.sync.aligned.m16n8k16.row.col.f32.bf16.bf16.f32 "
        "{%0,%1,%2,%3}, {%4,%5,%6,%7}, {%8,%9}, {%0,%1,%2,%3};"
        : "+f"(d[0]), "+f"(d[1]), "+f"(d[2]), "+f"(d[3])
        : "r"(a[0]), "r"(a[1]), "r"(a[2]), "r"(a[3]), "r"(b0), "r"(b1));
}
__device__ __forceinline__ float ex2f(float x) {
    float y;
    asm("ex2.approx.ftz.f32 %0, %1;" : "=f"(y) : "f"(x));
    return y;
}
__device__ __forceinline__ uint32_t cvt2(float a, float b) {   // bf16x2 {lo=a, hi=b}
    uint32_t r;
    asm("cvt.rn.bf16x2.f32 %0, %1, %2;" : "=r"(r) : "f"(b), "f"(a));
    return r;
}
__device__ __forceinline__ void split2(float a, float b, uint32_t& hw, uint32_t& lw) {
    hw = cvt2(a, b);
    float ha = __uint_as_float(hw << 16);
    float hb = __uint_as_float(hw & 0xffff0000u);
    lw = cvt2(a - ha, b - hb);
}

// ---------------------------------------------------------------------------
// Prep kernels
// ---------------------------------------------------------------------------
__global__ void prep_w_kernel(const float* __restrict__ Wt, const float* __restrict__ Wp,
                              const float* __restrict__ Wg, const float* __restrict__ Wo) {
    int r = blockIdx.x, c = threadIdx.x;
    if (r < 192) {
        float v = (r < 32) ? Wt[r * CHN + c]
                 : (r < 64) ? Wp[(r - 32) * CHN + c]
                            : Wg[(r - 64) * CHN + c];
        __nv_bfloat16 h = __float2bfloat16(v);
        g_wch[r * CHN + c] = h;
        g_wcl[r * CHN + c] = __float2bfloat16(v - __bfloat162float(h));
    } else if (c < 128) {
        int rr = r - 192;
        float v = Wo[rr * DV + c];
        __nv_bfloat16 h = __float2bfloat16(v);
        g_woh[rr * DV + c] = h;
        g_wol[rr * DV + c] = __float2bfloat16(v - __bfloat162float(h));
    }
}

// x [b][256][4096] -> x^T hi/lo [b][4096][256]
__global__ void transpose_x_kernel(const float* __restrict__ Xg) {
    __shared__ float tile[32][33];
    int b  = blockIdx.z;
    int n0 = blockIdx.x * 32;
    int c0 = blockIdx.y * 32;
    int tx = threadIdx.x & 31, ty = threadIdx.x >> 5;
    const float* xb = Xg + (size_t)b * CHN * SEQ;
#pragma unroll
    for (int i = 0; i < 32; i += 8)
        tile[ty + i][tx] = xb[(size_t)(c0 + ty + i) * SEQ + n0 + tx];
    __syncthreads();
#pragma unroll
    for (int i = 0; i < 32; i += 8) {
        float v = tile[tx][ty + i];
        __nv_bfloat16 h = __float2bfloat16(v);
        size_t off = ((size_t)b * SEQ + n0 + ty + i) * CHN + c0 + tx;
        g_xth[off] = h;
        g_xtl[off] = __float2bfloat16(v - __bfloat162float(h));
    }
}

// ---------------------------------------------------------------------------
// Projection GEMM via mma.sync: C[n][out192] = x^T[n][c] * Wcat[out][c]
// ---------------------------------------------------------------------------
#define PJ_SMEM 110592
__global__ __launch_bounds__(256, 1) void proj_mma_kernel() {
    extern __shared__ char sm[];
    const uint32_t smb = smem_u32(sm);
    const int b    = blockIdx.z;
    const int out0 = blockIdx.y * 64;
    const int n0   = blockIdx.x * 128;
    const int tid  = threadIdx.x;
    const int w    = tid >> 5;
    const int lane = tid & 31;
    const uint32_t lm = lane & 7;
    const uint32_t bk = (lane >> 3) & 1;
    const uint32_t bn = (lane >> 4) & 1;

    auto load_chunk = [&](int buf, int k0) {
        uint32_t base = smb + buf * 55296;
        const char* xh = (const char*)(g_xth + ((size_t)b * SEQ + n0) * CHN + k0);
        const char* xl = (const char*)(g_xtl + ((size_t)b * SEQ + n0) * CHN + k0);
        for (int e = tid; e < 1024; e += 256) {
            int r = e >> 3, s = e & 7;
            cpa16(base + r * 144 + s * 16,         xh + (size_t)r * 512 + s * 16);
            cpa16(base + 18432 + r * 144 + s * 16, xl + (size_t)r * 512 + s * 16);
        }
        const char* wh = (const char*)(g_wch + (size_t)out0 * CHN + k0);
        const char* wl = (const char*)(g_wcl + (size_t)out0 * CHN + k0);
        for (int e = tid; e < 512; e += 256) {
            int r = e >> 3, s = e & 7;
            cpa16(base + 36864 + r * 144 + s * 16, wh + (size_t)r * 512 + s * 16);
            cpa16(base + 46080 + r * 144 + s * 16, wl + (size_t)r * 512 + s * 16);
        }
    };

    float oacc[8][4];
#pragma unroll
    for (int g = 0; g < 8; g++)
#pragma unroll
        for (int k = 0; k < 4; k++) oacc[g][k] = 0.f;

    load_chunk(0, 0);
    CP_COMMIT();

    for (int kb = 0; kb < 4; kb++) {
        int buf = kb & 1;
        if (kb < 3) { load_chunk(buf ^ 1, (kb + 1) * 64); CP_COMMIT(); CP_WAIT1(); }
        else        { CP_WAIT0(); }
        __syncthreads();

        uint32_t ab = smb + buf * 55296;
        uint32_t bb = ab + 36864;
#pragma unroll
        for (int kc = 0; kc < 4; kc++) {
            uint32_t ah4[4], al4[4];
            uint32_t aaddr = ab + (w * 16 + bk * 8 + lm) * 144 + (kc * 16 + bn * 8) * 2;
            ldsm4(ah4, aaddr);
            ldsm4(al4, aaddr + 18432);
#pragma unroll
            for (int jj = 0; jj < 4; jj++) {
                uint32_t baddr = bb + (jj * 16 + bn * 8 + lm) * 144 + (kc * 16 + bk * 8) * 2;
                uint32_t bh4[4], bl4[4];
                ldsm4(bh4, baddr);
                ldsm4(bl4, baddr + 9216);
                mma_bf16(oacc[2 * jj],     ah4, bh4[0], bh4[1]);
                mma_bf16(oacc[2 * jj],     ah4, bl4[0], bl4[1]);
                mma_bf16(oacc[2 * jj],     al4, bh4[0], bh4[1]);
                mma_bf16(oacc[2 * jj + 1], ah4, bh4[2], bh4[3]);
                mma_bf16(oacc[2 * jj + 1], ah4, bl4[2], bl4[3]);
                mma_bf16(oacc[2 * jj + 1], al4, bh4[2], bh4[3]);
            }
        }
        __syncthreads();
    }

    // epilogue
    const int rbase = n0 + w * 16 + (lane >> 2);
    const int qc = (lane & 3) * 2;
#pragma unroll
    for (int g = 0; g < 8; g++) {
        int out = out0 + g * 8 + qc;
#pragma unroll
        for (int rr = 0; rr < 2; rr++) {
            int n = rbase + rr * 8;
            float v0 = oacc[g][rr * 2], v1 = oacc[g][rr * 2 + 1];
            uint32_t hw, lw;
            if (out < 32) {
                split2(v0, v1, hw, lw);
                __nv_bfloat16* base = g_th_t + ((size_t)b * SEQ + n) * 64;
                *(uint32_t*)(base + out) = hw;
                *(uint32_t*)(base + 32 + out) = lw;
            } else if (out < 64) {
                split2(v0 * LOG2E, v1 * LOG2E, hw, lw);
                __nv_bfloat16* base = g_ph_t + ((size_t)b * SEQ + n) * 64;
                *(uint32_t*)(base + (out - 32)) = hw;
                *(uint32_t*)(base + out) = lw;
            } else {
                size_t off = ((size_t)b * SEQ + n) * DV + (out - 64);
                *(uint32_t*)(g_vth + off) = cvt2(v0, v1);   // bf16 hi only
            }
        }
    }
}

// ---------------------------------------------------------------------------
// Flash attention (mma.sync; S 3-term bf16, PV (ph+pl)*vh, no-max softmax).
// FINE-GRAINED PIPELINE: per 16-key slice jj, do S-MMA(jj) -> exp/split(8) ->
// PV-MMA(kk=jj) immediately. Short MUFU bursts hide under the partner warp's
// MMA bursts; first PV issues after 8 exps instead of 32.
// 4-deep K/V buffers, 2 tiles per __syncthreads (round-14 structure, no swap).
// Smem: QHI 0..10240 QLO 10240..20480 (80B rows)
//       K buf b: 20480 + b*10240 (hi, +5120 lo), b in 0..3
//       V buf b: 61440 + b*17408 ([64 m][272B] bf16 hi), b in 0..3
// Total 131072 (1 CTA/SM).
// ---------------------------------------------------------------------------
#define SM_QHI 0
#define SM_QLO 10240
#define SM_K   20480
#define SM_V   61440
#define FLASH_SMEM 131072

__global__ __launch_bounds__(256, 1) void flash_mma_kernel() {
    extern __shared__ char sm[];
    const uint32_t smb = smem_u32(sm);

    const int b  = blockIdx.y;
    const int q0 = blockIdx.x * QT;
    const int tid  = threadIdx.x;
    const int w    = tid >> 5;
    const int lane = tid & 31;
    const uint32_t lm = lane & 7;
    const uint32_t bk = (lane >> 3) & 1;
    const uint32_t bn = (lane >> 4) & 1;

    auto load_kv = [&](int buf, int m0) {
        const char* ks = (const char*)(g_ph_t + ((size_t)b * SEQ + m0) * 64);
        uint32_t kb = smb + SM_K + buf * 10240;
        for (int e = tid; e < 512; e += 256) {
            int r = e >> 3, s = e & 7;
            uint32_t dst = kb + (s < 4 ? (r * 80 + s * 16) : (5120 + r * 80 + (s - 4) * 16));
            cpa16(dst, ks + r * 128 + s * 16);
        }
        const char* vh = (const char*)(g_vth + ((size_t)b * SEQ + m0) * DV);
        uint32_t vb = smb + SM_V + buf * 17408;
        for (int e = tid; e < 1024; e += 256) {
            int r = e >> 4, s = e & 15;
            cpa16(vb + r * 272 + s * 16, vh + (size_t)r * 256 + s * 16);
        }
    };

    // Q tile + first two K/V tiles
    {
        const char* src = (const char*)(g_th_t + ((size_t)b * SEQ + q0) * 64);
        for (int e = tid; e < 1024; e += 256) {
            int r = e >> 3, s = e & 7;
            uint32_t dst = smb + (s < 4 ? (SM_QHI + r * 80 + s * 16)
                                        : (SM_QLO + r * 80 + (s - 4) * 16));
            cpa16(dst, src + r * 128 + s * 16);
        }
    }
    load_kv(0, 0);
    CP_COMMIT();
    load_kv(1, MT);
    CP_COMMIT();
    CP_WAIT0();
    __syncthreads();

    uint32_t qh[2][4], ql[2][4];
#pragma unroll
    for (int ks = 0; ks < 2; ks++) {
        uint32_t a = smb + SM_QHI + (w * 16 + bk * 8 + lm) * 80 + (ks * 16 + bn * 8) * 2;
        ldsm4(qh[ks], a);
        ldsm4(ql[ks], a + (SM_QLO - SM_QHI));
    }

    float oacc[16][4];
#pragma unroll
    for (int j = 0; j < 16; j++)
#pragma unroll
        for (int k = 0; k < 4; k++) oacc[j][k] = 0.f;
    float l0 = 0.f, l1 = 0.f;

    // process one tile from buffer `buf` -- fine-grained S->softmax->PV slices
    auto proc_tile = [&](int buf) {
        const uint32_t kb = smb + SM_K + buf * 10240;
        const uint32_t vb = smb + SM_V + buf * 17408;
#pragma unroll
        for (int jj = 0; jj < 4; jj++) {
            // S slice: key cols 16*jj .. 16*jj+15 (3-term bf16)
            float s0[4] = {0.f, 0.f, 0.f, 0.f};
            float s1[4] = {0.f, 0.f, 0.f, 0.f};
#pragma unroll
            for (int ks = 0; ks < 2; ks++) {
                uint32_t addr = kb + (jj * 16 + bn * 8 + lm) * 80 + (ks * 16 + bk * 8) * 2;
                uint32_t kh[4], kl[4];
                ldsm4(kh, addr);
                ldsm4(kl, addr + 5120);
                mma_bf16(s0, qh[ks], kh[0], kh[1]);
                mma_bf16(s0, qh[ks], kl[0], kl[1]);
                mma_bf16(s0, ql[ks], kh[0], kh[1]);
                mma_bf16(s1, qh[ks], kh[2], kh[3]);
                mma_bf16(s1, qh[ks], kl[2], kl[3]);
                mma_bf16(s1, ql[ks], kh[2], kh[3]);
            }

            // softmax slice: 8 exps + hi/lo split (phi prescaled by log2e)
            uint32_t pah[4], pal[4];
            {
                float p0 = ex2f(s0[0]), p1 = ex2f(s0[1]);
                float p2 = ex2f(s0[2]), p3 = ex2f(s0[3]);
                l0 += p0 + p1;
                l1 += p2 + p3;
                split2(p0, p1, pah[0], pal[0]);
                split2(p2, p3, pah[1], pal[1]);
                p0 = ex2f(s1[0]); p1 = ex2f(s1[1]);
                p2 = ex2f(s1[2]); p3 = ex2f(s1[3]);
                l0 += p0 + p1;
                l1 += p2 + p3;
                split2(p0, p1, pah[2], pal[2]);
                split2(p2, p3, pah[3], pal[3]);
            }

            // PV slice: O += P(kk=jj) V^T, all 8 channel chunks
#pragma unroll
            for (int c8 = 0; c8 < 8; c8++) {
                uint32_t addr = vb + (jj * 16 + bk * 8 + lm) * 272 + (c8 * 16 + bn * 8) * 2;
                uint32_t vh4[4];
                ldsm4_t(vh4, addr);
                mma_bf16(oacc[2 * c8],     pah, vh4[0], vh4[1]);
                mma_bf16(oacc[2 * c8],     pal, vh4[0], vh4[1]);
                mma_bf16(oacc[2 * c8 + 1], pah, vh4[2], vh4[3]);
                mma_bf16(oacc[2 * c8 + 1], pal, vh4[2], vh4[3]);
            }
        }
    };

    for (int it = 0; it < NTILE; it += 2) {
        // tiles it, it+1 are resident; prefetch it+2, it+3
        if (it + 2 < NTILE) { load_kv((it + 2) & 3, (it + 2) * MT); CP_COMMIT(); }
        if (it + 3 < NTILE) { load_kv((it + 3) & 3, (it + 3) * MT); CP_COMMIT(); }

        proc_tile(it & 3);
        proc_tile((it + 1) & 3);

        CP_WAIT0();
        __syncthreads();
    }

    // epilogue: reduce row sums, normalize, write attn^T hi/lo bf16
    l0 += __shfl_xor_sync(0xffffffffu, l0, 1);
    l0 += __shfl_xor_sync(0xffffffffu, l0, 2);
    l1 += __shfl_xor_sync(0xffffffffu, l1, 1);
    l1 += __shfl_xor_sync(0xffffffffu, l1, 2);
    const float inv0 = 1.f / l0;
    const float inv1 = 1.f / l1;

    const int r0 = q0 + w * 16 + (lane >> 2);
    const int qc = (lane & 3) * 2;
#pragma unroll
    for (int j = 0; j < 16; j++) {
        int c = j * 8 + qc;
        uint32_t hw, lw;
        split2(oacc[j][0] * inv0, oacc[j][1] * inv0, hw, lw);
        size_t off = ((size_t)b * SEQ + r0) * DV + c;
        *(uint32_t*)(g_ath + off) = hw;
        *(uint32_t*)(g_atl + off) = lw;
        split2(oacc[j][2] * inv1, oacc[j][3] * inv1, hw, lw);
        size_t off2 = ((size_t)b * SEQ + r0 + 8) * DV + c;
        *(uint32_t*)(g_ath + off2) = hw;
        *(uint32_t*)(g_atl + off2) = lw;
    }
}

// ---------------------------------------------------------------------------
// Output GEMM via mma.sync
// ---------------------------------------------------------------------------
#define OM_SMEM 104448
__global__ __launch_bounds__(256) void out_mma_kernel(const float* __restrict__ Xg,
                                                      float* __restrict__ Cg,
                                                      const float* __restrict__ gamma_p) {
    extern __shared__ char sm[];
    const uint32_t smb = smem_u32(sm);
    const int b  = blockIdx.z;
    const int n0 = blockIdx.x * 64;
    const int m0 = blockIdx.y * 128;
    const int tid  = threadIdx.x;
    const int w    = tid >> 5;
    const int lane = tid & 31;
    const uint32_t lm = lane & 7;
    const uint32_t bk = (lane >> 3) & 1;
    const uint32_t bn = (lane >> 4) & 1;

    {
        const char* ah = (const char*)(g_woh + (size_t)m0 * DV);
        const char* al = (const char*)(g_wol + (size_t)m0 * DV);
        for (int e = tid; e < 2048; e += 256) {
            int r = e >> 4, s = e & 15;
            cpa16(smb + r * 272 + s * 16,         ah + (size_t)r * 256 + s * 16);
            cpa16(smb + 34816 + r * 272 + s * 16, al + (size_t)r * 256 + s * 16);
        }
        const char* bh = (const char*)(g_ath + ((size_t)b * SEQ + n0) * DV);
        const char* bl = (const char*)(g_atl + ((size_t)b * SEQ + n0) * DV);
        for (int e = tid; e < 1024; e += 256) {
            int r = e >> 4, s = e & 15;
            cpa16(smb + 69632 + r * 272 + s * 16, bh + (size_t)r * 256 + s * 16);
            cpa16(smb + 87040 + r * 272 + s * 16, bl + (size_t)r * 256 + s * 16);
        }
    }
    CP_COMMIT();
    CP_WAIT0();
    __syncthreads();

    float oacc[8][4];
#pragma unroll
    for (int g = 0; g < 8; g++)
#pragma unroll
        for (int k = 0; k < 4; k++) oacc[g][k] = 0.f;

#pragma unroll
    for (int kc = 0; kc < 8; kc++) {
        uint32_t ah4[4], al4[4];
        uint32_t aaddr = smb + (w * 16 + bk * 8 + lm) * 272 + (kc * 16 + bn * 8) * 2;
        ldsm4(ah4, aaddr);
        ldsm4(al4, aaddr + 34816);
#pragma unroll
        for (int jj = 0; jj < 4; jj++) {
            uint32_t baddr = smb + 69632 + (jj * 16 + bn * 8 + lm) * 272 + (kc * 16 + bk * 8) * 2;
            uint32_t bh4[4], bl4[4];
            ldsm4(bh4, baddr);
            ldsm4(bl4, baddr + 17408);
            mma_bf16(oacc[2 * jj],     ah4, bh4[0], bh4[1]);
            mma_bf16(oacc[2 * jj],     ah4, bl4[0], bl4[1]);
            mma_bf16(oacc[2 * jj],     al4, bh4[0], bh4[1]);
            mma_bf16(oacc[2 * jj + 1], ah4, bh4[2], bh4[3]);
            mma_bf16(oacc[2 * jj + 1], ah4, bl4[2], bl4[3]);
            mma_bf16(oacc[2 * jj + 1], al4, bh4[2], bh4[3]);
        }
    }

    const float gm = gamma_p[0];
    const float* xb = Xg + (size_t)b * CHN * SEQ;
    float* cb = Cg + (size_t)b * CHN * SEQ;
    const int r = m0 + w * 16 + (lane >> 2);
    const int qc = (lane & 3) * 2;
#pragma unroll
    for (int g = 0; g < 8; g++) {
        int n = n0 + g * 8 + qc;
#pragma unroll
        for (int rr = 0; rr < 2; rr++) {
            int row = r + rr * 8;
            float2 x2 = *(const float2*)(xb + (size_t)row * SEQ + n);
            float2 o;
            o.x = gm * oacc[g][rr * 2]     + x2.x;
            o.y = gm * oacc[g][rr * 2 + 1] + x2.y;
            *(float2*)(cb + (size_t)row * SEQ + n) = o;
        }
    }
}

// ---------------------------------------------------------------------------
// Launch
// ---------------------------------------------------------------------------
extern "C" void kernel_launch(void* const* d_in, const int* in_sizes, int n_in,
                              void* d_out, int out_size) {
    const float* x     = (const float*)d_in[0];
    const float* Wt    = (const float*)d_in[1];
    const float* Wp    = (const float*)d_in[2];
    const float* Wg    = (const float*)d_in[3];
    const float* Wo    = (const float*)d_in[4];
    const float* gamma = (const float*)d_in[5];
    float* out = (float*)d_out;
    (void)in_sizes; (void)n_in; (void)out_size;

    prep_w_kernel<<<448, 256>>>(Wt, Wp, Wg, Wo);
    transpose_x_kernel<<<dim3(SEQ / 32, CHN / 32, BATCH), 256>>>(x);

    cudaFuncSetAttribute(proj_mma_kernel, cudaFuncAttributeMaxDynamicSharedMemorySize, PJ_SMEM);
    proj_mma_kernel<<<dim3(SEQ / 128, 3, BATCH), 256, PJ_SMEM>>>();

    cudaFuncSetAttribute(flash_mma_kernel, cudaFuncAttributeMaxDynamicSharedMemorySize, FLASH_SMEM);
    flash_mma_kernel<<<dim3(SEQ / QT, BATCH), 256, FLASH_SMEM>>>();

    cudaFuncSetAttribute(out_mma_kernel, cudaFuncAttributeMaxDynamicSharedMemorySize, OM_SMEM);
    out_mma_kernel<<<dim3(SEQ / 64, CHN / 128, BATCH), 256, OM_SMEM>>>(x, out, gamma);
}